// round 14
// baseline (speedup 1.0000x reference)
#include <cuda_runtime.h>
#include <cstdint>
#include <cstddef>

// ---------------------------------------------------------------------------
// Problem constants
// ---------------------------------------------------------------------------
#define VOCAB   16384
#define DDIM    1024
#define BATCH   8
#define TSTEPS  16
#define NLAYERS 4
#define LFSR_POLY 0x100Bu           // 69643 & 0xFFFF (bits 0,1,3,12)
#define SEEDS_PER_LAYER 65536

// toks [T,B] (as float) followed by logits [T,B,V] in d_out (float32)
#define TOKS_COUNT (TSTEPS*BATCH)

#define NTHREADS 512
#define NWARPS   16

// ---------------------------------------------------------------------------
// Device scratch (static globals: allocation-free)
// ---------------------------------------------------------------------------
// signed-int8 weight planes: klo_s = (k&255)-128, khi_s = (k>>8)-128
__device__ unsigned char g_wlo[(size_t)NLAYERS * VOCAB * DDIM];  // 64 MB
__device__ unsigned char g_whi[(size_t)NLAYERS * VOCAB * DDIM];  // 64 MB
__device__ unsigned long long g_bestA[TSTEPS * BATCH];  // per-step packed (ordered_val<<32)|(~v)

// ---------------------------------------------------------------------------
// threefry2x32-20 (exact JAX implementation), host+device
// ---------------------------------------------------------------------------
__host__ __device__ __forceinline__ unsigned rotl32(unsigned x, int r) {
#ifdef __CUDA_ARCH__
    return __funnelshift_l(x, x, r);
#else
    return (x << r) | (x >> (32 - r));
#endif
}

__host__ __device__ __forceinline__ uint2 threefry2x32(uint2 key, unsigned c0, unsigned c1) {
    unsigned ks0 = key.x, ks1 = key.y;
    unsigned ks2 = ks0 ^ ks1 ^ 0x1BD11BDAu;
    unsigned x0 = c0 + ks0;
    unsigned x1 = c1 + ks1;
#define TF_R4(a,b,c,d)                                              \
    x0 += x1; x1 = rotl32(x1,(a)); x1 ^= x0;                        \
    x0 += x1; x1 = rotl32(x1,(b)); x1 ^= x0;                        \
    x0 += x1; x1 = rotl32(x1,(c)); x1 ^= x0;                        \
    x0 += x1; x1 = rotl32(x1,(d)); x1 ^= x0;
    TF_R4(13,15,26,6);   x0 += ks1; x1 += ks2 + 1u;
    TF_R4(17,29,16,24);  x0 += ks2; x1 += ks0 + 2u;
    TF_R4(13,15,26,6);   x0 += ks0; x1 += ks1 + 3u;
    TF_R4(17,29,16,24);  x0 += ks1; x1 += ks2 + 4u;
    TF_R4(13,15,26,6);   x0 += ks2; x1 += ks0 + 5u;
#undef TF_R4
    uint2 out; out.x = x0; out.y = x1; return out;
}

// ordered-uint encoding of float for monotone unsigned compare
__device__ __forceinline__ unsigned orderf(float f) {
    unsigned u = __float_as_uint(f);
    return (u & 0x80000000u) ? ~u : (u | 0x80000000u);
}

__device__ __forceinline__ float decode_tok(unsigned long long k) {
    return (float)(0xFFFFFFFFu - (unsigned)(k & 0xFFFFFFFFu));
}

// ---------------------------------------------------------------------------
// Kernel 0: zero the argmax table (head of every replay -> deterministic)
// ---------------------------------------------------------------------------
__global__ void init_kernel() {
    int i = threadIdx.x;
    if (i < TSTEPS * BATCH) g_bestA[i] = 0ull;
}

// ---------------------------------------------------------------------------
// Kernel 1: fused step kernel. 128 blocks x 512 threads, 128 vocab rows/block
// (2 rows/thread; warp = 8 rows: g = lane>>3 -> 2-row group, j = lane&7 ->
// d-slice). __launch_bounds__(512, 2) forces <=64 regs -> 2 blocks/SM.
//   (gen, t<4 only) each thread LFSR-decompresses ONE seed into the s8
//       planes (block's own tile); later steps reuse them.
//   (a) inline prep: layernorm + int8 quantize -> packed q, Sq, 1/as
//   (b) dp4a integer matmul on the two s8 planes
//   (c) fused gumbel-argmax -> atomicMax g_bestA[t]
// q smem layout: slot o = 32m + jj + 8*e4 for d4 = 32m + 4jj + e4
// -> conflict-free LDS.128 across the 8 j-lanes.
// ---------------------------------------------------------------------------
__global__ void __launch_bounds__(NTHREADS, 2) step_kernel(int t, const float* __restrict__ scales,
                                                           float* __restrict__ d_out,
                                                           unsigned skx, unsigned sky,
                                                           const float* __restrict__ x0,
                                                           const int* __restrict__ seeds) {
    __shared__ uint4 s_qA[256];                     // packed q, b0..3, 4 KB
    __shared__ uint4 s_qB[256];                     // packed q, b4..7, 4 KB
    __shared__ float s_lg[128 * 9];                 // logits [v_local][b], padded
    __shared__ float s_red[NWARPS][8];
    __shared__ float s_bc[8];                       // broadcast: mu / rstd / as
    __shared__ float s_sq[8];                       // Sq[b] (exact in float)
    __shared__ float s_inv[8];                      // 1/as[b]
    __shared__ unsigned long long s_wbest[NWARPS][2];

    const int tid  = threadIdx.x;
    const int warp = tid >> 5;
    const int lane = tid & 31;
    const int l    = t & 3;

    // ================= (gen) inline tile decompression, steps 0-3 =================
    // Block's tile = rows [blockIdx.x*128, +128) of layer l = seeds
    // [l*65536 + blockIdx.x*512, +512). One seed per thread.
    if (t < 4) {
        const int sid = l * SEEDS_PER_LAYER + blockIdx.x * 512 + tid;
        unsigned state = ((unsigned)seeds[sid]) & 0xFFFFu;
        uint4* lo = reinterpret_cast<uint4*>(g_wlo + (size_t)sid * 256);
        uint4* hi = reinterpret_cast<uint4*>(g_whi + (size_t)sid * 256);
#pragma unroll 4
        for (int m = 0; m < 16; m++) {
            unsigned wl[4] = {0u, 0u, 0u, 0u};
            unsigned wh[4] = {0u, 0u, 0u, 0u};
#pragma unroll
            for (int e = 0; e < 16; e++) {
                unsigned bl = (state & 0xFFu) ^ 0x80u;          // klo - 128 as s8
                unsigned bh = ((state >> 8) & 0xFFu) ^ 0x80u;   // khi - 128 as s8
                wl[e >> 2] |= bl << ((e & 3) * 8);
                wh[e >> 2] |= bh << ((e & 3) * 8);
                unsigned fb = __popc(state & LFSR_POLY) & 1u;
                state = ((state >> 1) | (fb << 15)) & 0xFFFFu;
            }
            uint4 ul; ul.x = wl[0]; ul.y = wl[1]; ul.z = wl[2]; ul.w = wl[3];
            uint4 uh; uh.x = wh[0]; uh.y = wh[1]; uh.z = wh[2]; uh.w = wh[3];
            lo[m] = ul;
            hi[m] = uh;
        }
    }

    // ================= inline prep =================
    // thread handles d0 = 2*tid, d1 = 2*tid+1
    float v[2][8];
#pragma unroll
    for (int k = 0; k < 2; k++) {
        const int d = 2 * tid + k;
        if (d < DDIM - t) {
#pragma unroll
            for (int b = 0; b < 8; b++) v[k][b] = x0[b * DDIM + d + t];
        } else {
            const int s = d + t - DDIM;   // 0..t-1
#pragma unroll
            for (int b = 0; b < 8; b++) v[k][b] = decode_tok(g_bestA[s * BATCH + b]);
        }
    }

    // ---- mean ----
    float part[8];
#pragma unroll
    for (int b = 0; b < 8; b++) part[b] = v[0][b] + v[1][b];
#pragma unroll
    for (int off = 16; off; off >>= 1)
#pragma unroll
        for (int b = 0; b < 8; b++) part[b] += __shfl_down_sync(0xFFFFFFFFu, part[b], off);
    if (lane == 0)
#pragma unroll
        for (int b = 0; b < 8; b++) s_red[warp][b] = part[b];
    __syncthreads();
    if (warp == 0 && lane < 8) {
        const int b = lane;
        float s = 0.0f;
#pragma unroll
        for (int w = 0; w < NWARPS; w++) s += s_red[w][b];
        s_bc[b] = s * (1.0f / DDIM);
    }
    __syncthreads();
    float mu[8];
#pragma unroll
    for (int b = 0; b < 8; b++) mu[b] = s_bc[b];
    __syncthreads();

    // ---- variance ----
#pragma unroll
    for (int b = 0; b < 8; b++) {
        float d0 = v[0][b] - mu[b], d1 = v[1][b] - mu[b];
        part[b] = d0 * d0 + d1 * d1;
    }
#pragma unroll
    for (int off = 16; off; off >>= 1)
#pragma unroll
        for (int b = 0; b < 8; b++) part[b] += __shfl_down_sync(0xFFFFFFFFu, part[b], off);
    if (lane == 0)
#pragma unroll
        for (int b = 0; b < 8; b++) s_red[warp][b] = part[b];
    __syncthreads();
    if (warp == 0 && lane < 8) {
        const int b = lane;
        float s = 0.0f;
#pragma unroll
        for (int w = 0; w < NWARPS; w++) s += s_red[w][b];
        s_bc[b] = 1.0f / sqrtf(s * (1.0f / DDIM) + 1e-5f);
    }
    __syncthreads();
    float xn[2][8];
#pragma unroll
    for (int k = 0; k < 2; k++)
#pragma unroll
        for (int b = 0; b < 8; b++) xn[k][b] = (v[k][b] - mu[b]) * s_bc[b];
    __syncthreads();

    // ---- max |xn| ----
#pragma unroll
    for (int b = 0; b < 8; b++) part[b] = fmaxf(fabsf(xn[0][b]), fabsf(xn[1][b]));
#pragma unroll
    for (int off = 16; off; off >>= 1)
#pragma unroll
        for (int b = 0; b < 8; b++) part[b] = fmaxf(part[b], __shfl_down_sync(0xFFFFFFFFu, part[b], off));
    if (lane == 0)
#pragma unroll
        for (int b = 0; b < 8; b++) s_red[warp][b] = part[b];
    __syncthreads();
    if (warp == 0 && lane < 8) {
        const int b = lane;
        float s = s_red[0][b];
#pragma unroll
        for (int w = 1; w < NWARPS; w++) s = fmaxf(s, s_red[w][b]);
        float as = 127.0f / fmaxf(s, 1e-5f);
        s_bc[b]  = as;
        s_inv[b] = 1.0f / as;
    }
    __syncthreads();

    // ---- int8 quantize ----
    int q[2][8];
#pragma unroll
    for (int k = 0; k < 2; k++)
#pragma unroll
        for (int b = 0; b < 8; b++)
            q[k][b] = (int)rintf(fminf(fmaxf(xn[k][b] * s_bc[b], -127.0f), 127.0f));

    // ---- Sq[b] reduction (exact in fp32) ----
#pragma unroll
    for (int b = 0; b < 8; b++) part[b] = (float)(q[0][b] + q[1][b]);
#pragma unroll
    for (int off = 16; off; off >>= 1)
#pragma unroll
        for (int b = 0; b < 8; b++) part[b] += __shfl_down_sync(0xFFFFFFFFu, part[b], off);
    if (lane == 0)
#pragma unroll
        for (int b = 0; b < 8; b++) s_red[warp][b] = part[b];
    __syncthreads();
    if (warp == 0 && lane < 8) {
        const int b = lane;
        float s = 0.0f;
#pragma unroll
        for (int w = 0; w < NWARPS; w++) s += s_red[w][b];
        s_sq[b] = s;
    }

    // ---- pack q (4 consecutive d per u32) and store swizzled ----
    {
        unsigned half[8], other[8];
#pragma unroll
        for (int b = 0; b < 8; b++)
            half[b] = (unsigned)(q[0][b] & 0xFF) | ((unsigned)(q[1][b] & 0xFF) << 8);
#pragma unroll
        for (int b = 0; b < 8; b++)
            other[b] = __shfl_down_sync(0xFFFFFFFFu, half[b], 1);
        if ((tid & 1) == 0) {
            const int d4 = tid >> 1;              // 0..255
            const int m  = d4 >> 5;
            const int i  = d4 & 31;
            const int jj = i >> 2;
            const int e4 = i & 3;
            const int o  = 32 * m + jj + 8 * e4;
            uint4 qa, qb;
            qa.x = half[0] | (other[0] << 16);
            qa.y = half[1] | (other[1] << 16);
            qa.z = half[2] | (other[2] << 16);
            qa.w = half[3] | (other[3] << 16);
            qb.x = half[4] | (other[4] << 16);
            qb.y = half[5] | (other[5] << 16);
            qb.z = half[6] | (other[6] << 16);
            qb.w = half[7] | (other[7] << 16);
            s_qA[o] = qa;
            s_qB[o] = qb;
        }
    }
    __syncthreads();

    // ================= dp4a matmul =================
    // warp covers 8 rows; lane (g, j): g = lane>>3 -> 2 rows, j = lane&7 -> d-slice
    const int g   = lane >> 3;
    const int j   = lane & 7;
    const int vl0 = warp * 8 + g * 2;
    const int v0  = blockIdx.x * 128 + vl0;

    const uint4* lo0 = reinterpret_cast<const uint4*>(
        g_wlo + ((size_t)l * VOCAB + v0) * DDIM);   // 64 uint4 per row
    const uint4* hi0 = reinterpret_cast<const uint4*>(
        g_whi + ((size_t)l * VOCAB + v0) * DDIM);

    int accL[2][8], accH[2][8];
#pragma unroll
    for (int r = 0; r < 2; r++)
#pragma unroll
        for (int b = 0; b < 8; b++) { accL[r][b] = 0; accH[r][b] = 0; }

#pragma unroll 2
    for (int m = 0; m < 8; m++) {
        const int c = j + 8 * m;                  // uint4 index within row
        uint4 L0 = lo0[c];
        uint4 L1 = lo0[c + 64];
        uint4 H0 = hi0[c];
        uint4 H1 = hi0[c + 64];
        unsigned Lw[2][4] = {{L0.x, L0.y, L0.z, L0.w}, {L1.x, L1.y, L1.z, L1.w}};
        unsigned Hw[2][4] = {{H0.x, H0.y, H0.z, H0.w}, {H1.x, H1.y, H1.z, H1.w}};
#pragma unroll
        for (int e4 = 0; e4 < 4; e4++) {
            const int o = 32 * m + j + 8 * e4;
            const uint4 qa = s_qA[o];
            const uint4 qb = s_qB[o];
            const int qv[8] = {(int)qa.x, (int)qa.y, (int)qa.z, (int)qa.w,
                               (int)qb.x, (int)qb.y, (int)qb.z, (int)qb.w};
#pragma unroll
            for (int r = 0; r < 2; r++) {
                const int wl = (int)Lw[r][e4];
                const int wh = (int)Hw[r][e4];
#pragma unroll
                for (int b = 0; b < 8; b++) {
                    accL[r][b] = __dp4a(qv[b], wl, accL[r][b]);
                    accH[r][b] = __dp4a(qv[b], wh, accH[r][b]);
                }
            }
        }
    }

    // reduce over the 8 D-slice lanes (groups of 8 within the warp)
#pragma unroll
    for (int r = 0; r < 2; r++)
#pragma unroll
        for (int b = 0; b < 8; b++) {
            int aL = accL[r][b], aH = accH[r][b];
            aL += __shfl_down_sync(0xFFFFFFFFu, aL, 4, 8);
            aL += __shfl_down_sync(0xFFFFFFFFu, aL, 2, 8);
            aL += __shfl_down_sync(0xFFFFFFFFu, aL, 1, 8);
            aH += __shfl_down_sync(0xFFFFFFFFu, aH, 4, 8);
            aH += __shfl_down_sync(0xFFFFFFFFu, aH, 2, 8);
            aH += __shfl_down_sync(0xFFFFFFFFu, aH, 1, 8);
            accL[r][b] = aL; accH[r][b] = aH;
        }

    const float cl = scales[l] * (1.0f / 32768.0f);
    if (j == 0) {
#pragma unroll
        for (int r = 0; r < 2; r++) {
            const int vl = vl0 + r;
            const int vg = blockIdx.x * 128 + vl;
#pragma unroll
            for (int b = 0; b < 8; b++) {
                // k-32768 = 256*khi_s + klo_s + 128
                float S = fmaf(256.0f, (float)accH[r][b],
                               fmaf(128.0f, s_sq[b], (float)accL[r][b]));
                float lgv = S * cl * s_inv[b];
                d_out[TOKS_COUNT + ((size_t)t * BATCH + b) * VOCAB + vg] = lgv;
                s_lg[vl * 9 + b] = lgv;
            }
        }
    }
    __syncthreads();

    // ================= fused gumbel + block argmax =================
    {
        const int v_local = tid & 127;
        const int bg      = tid >> 7;            // 0..3 -> b pair
        const int vg      = blockIdx.x * 128 + v_local;
        uint2 sk; sk.x = skx; sk.y = sky;

        unsigned long long key[2];
#pragma unroll
        for (int i = 0; i < 2; i++) {
            const int b = bg * 2 + i;
            const unsigned ctr = (unsigned)b * (unsigned)VOCAB + (unsigned)vg;
            uint2 rr = threefry2x32(sk, 0u, ctr);
            unsigned bits = rr.x ^ rr.y;
            float u01 = __uint_as_float((bits >> 9) | 0x3f800000u) - 1.0f;
            float u   = fmaxf(u01, 1.17549435e-38f);
            float gum = -logf(-logf(u));
            float val = s_lg[v_local * 9 + b] + gum;
            key[i] = ((unsigned long long)orderf(val) << 32)
                   | (unsigned long long)(0xFFFFFFFFu - (unsigned)vg);
        }
#pragma unroll
        for (int off = 16; off; off >>= 1)
#pragma unroll
            for (int i = 0; i < 2; i++) {
                unsigned long long o = __shfl_down_sync(0xFFFFFFFFu, key[i], off);
                if (o > key[i]) key[i] = o;
            }
        if (lane == 0) {
            s_wbest[warp][0] = key[0];
            s_wbest[warp][1] = key[1];
        }
    }
    __syncthreads();

    // warp 0 merges 16 warps x 2 keys -> 8 per-b bests -> atomicMax
    if (warp == 0) {
        const int w = lane >> 1;                  // source warp
        const int i = lane & 1;
        unsigned long long key = s_wbest[w][i];
        {
            unsigned long long o = __shfl_down_sync(0xFFFFFFFFu, key, 4, 8);
            if (o > key) key = o;
            o = __shfl_down_sync(0xFFFFFFFFu, key, 2, 8);
            if (o > key) key = o;
        }
        if ((lane & 7) < 2) {
            const int b = ((lane >> 3) << 1) | (lane & 1);
            atomicMax(&g_bestA[t * BATCH + b], key);
        }
    }
}

// ---------------------------------------------------------------------------
// Kernel 2: final token decode for all steps
// ---------------------------------------------------------------------------
__global__ void finalize_kernel(float* __restrict__ d_out) {
    int i = threadIdx.x;
    if (i < TSTEPS * BATCH) d_out[i] = decode_tok(g_bestA[i]);
}

// ---------------------------------------------------------------------------
// Launch: single stream, 18 nodes. Steps 0-3 decompress their own layer's
// weights inline (block == tile == 512 seeds); steps 4-15 reuse them.
// ---------------------------------------------------------------------------
extern "C" void kernel_launch(void* const* d_in, const int* in_sizes, int n_in,
                              void* d_out, int out_size) {
    const float* x0     = (const float*)d_in[0];   // [8,1024]
    const int*   seeds  = (const int*)d_in[1];     // [4,65536]
    const float* scales = (const float*)d_in[2];   // [4]
    float* out = (float*)d_out;

    // host-side subkey chain (input-independent, deterministic):
    // key_0 = key(1) = (0,1); each step: new_key = tf(key,0,0), sk = tf(key,0,1)
    unsigned skx[TSTEPS], sky[TSTEPS];
    {
        uint2 key; key.x = 0u; key.y = 1u;
        for (int t = 0; t < TSTEPS; t++) {
            uint2 nk = threefry2x32(key, 0u, 0u);
            uint2 sk = threefry2x32(key, 0u, 1u);
            skx[t] = sk.x; sky[t] = sk.y;
            key = nk;
        }
    }

    init_kernel<<<1, 128>>>();
    for (int t = 0; t < TSTEPS; t++) {
        step_kernel<<<VOCAB / 128, NTHREADS>>>(t, scales, out, skx[t], sky[t], x0, seeds);
    }
    finalize_kernel<<<1, 128>>>(out);
}

// round 15
// speedup vs baseline: 1.1785x; 1.1785x over previous
#include <cuda_runtime.h>
#include <cstdint>
#include <cstddef>

// ---------------------------------------------------------------------------
// Problem constants
// ---------------------------------------------------------------------------
#define VOCAB   16384
#define DDIM    1024
#define BATCH   8
#define TSTEPS  16
#define NLAYERS 4
#define LFSR_POLY 0x100Bu           // 69643 & 0xFFFF (bits 0,1,3,12)
#define SEEDS_PER_LAYER 65536

// toks [T,B] (as float) followed by logits [T,B,V] in d_out (float32)
#define TOKS_COUNT (TSTEPS*BATCH)

#define NTHREADS 1024
#define NWARPS   32

// ---------------------------------------------------------------------------
// Device scratch (static globals: allocation-free)
// ---------------------------------------------------------------------------
// signed-int8 weight planes: klo_s = (k&255)-128, khi_s = (k>>8)-128
__device__ unsigned char g_wlo[(size_t)NLAYERS * VOCAB * DDIM];  // 64 MB
__device__ unsigned char g_whi[(size_t)NLAYERS * VOCAB * DDIM];  // 64 MB
__device__ unsigned long long g_bestA[TSTEPS * BATCH];  // per-step packed (ordered_val<<32)|(~v)

// ---------------------------------------------------------------------------
// threefry2x32-20 (exact JAX implementation), host+device
// ---------------------------------------------------------------------------
__host__ __device__ __forceinline__ unsigned rotl32(unsigned x, int r) {
#ifdef __CUDA_ARCH__
    return __funnelshift_l(x, x, r);
#else
    return (x << r) | (x >> (32 - r));
#endif
}

__host__ __device__ __forceinline__ uint2 threefry2x32(uint2 key, unsigned c0, unsigned c1) {
    unsigned ks0 = key.x, ks1 = key.y;
    unsigned ks2 = ks0 ^ ks1 ^ 0x1BD11BDAu;
    unsigned x0 = c0 + ks0;
    unsigned x1 = c1 + ks1;
#define TF_R4(a,b,c,d)                                              \
    x0 += x1; x1 = rotl32(x1,(a)); x1 ^= x0;                        \
    x0 += x1; x1 = rotl32(x1,(b)); x1 ^= x0;                        \
    x0 += x1; x1 = rotl32(x1,(c)); x1 ^= x0;                        \
    x0 += x1; x1 = rotl32(x1,(d)); x1 ^= x0;
    TF_R4(13,15,26,6);   x0 += ks1; x1 += ks2 + 1u;
    TF_R4(17,29,16,24);  x0 += ks2; x1 += ks0 + 2u;
    TF_R4(13,15,26,6);   x0 += ks0; x1 += ks1 + 3u;
    TF_R4(17,29,16,24);  x0 += ks1; x1 += ks2 + 4u;
    TF_R4(13,15,26,6);   x0 += ks2; x1 += ks0 + 5u;
#undef TF_R4
    uint2 out; out.x = x0; out.y = x1; return out;
}

// ordered-uint encoding of float for monotone unsigned compare
__device__ __forceinline__ unsigned orderf(float f) {
    unsigned u = __float_as_uint(f);
    return (u & 0x80000000u) ? ~u : (u | 0x80000000u);
}

__device__ __forceinline__ float decode_tok(unsigned long long k) {
    return (float)(0xFFFFFFFFu - (unsigned)(k & 0xFFFFFFFFu));
}

// ---------------------------------------------------------------------------
// Kernel 0: zero the argmax table (head of every replay -> deterministic)
// ---------------------------------------------------------------------------
__global__ void init_kernel() {
    int i = threadIdx.x;
    if (i < TSTEPS * BATCH) g_bestA[i] = 0ull;
}

// ---------------------------------------------------------------------------
// Kernel 1: fused step kernel. 128 blocks x 1024 threads, 128 vocab rows/block
// (one row per thread; warp = 4 rows x 8 d-slices).
//   (gen, t<4 only) threads 0-511 LFSR-decompress one seed each into the
//       s8 planes via WRITE-THROUGH stores (lines land in L2 clean -> no
//       writeback storm under steps 4-7); later steps reuse them.
//   (a) inline prep: layernorm + int8 quantize -> packed q, Sq, 1/as
//   (b) dp4a integer matmul, weights read via __ldcs (streaming: reuse
//       distance 4 steps ~ 128 MB > L2, caching is pure pollution)
//   (c) fused gumbel-argmax -> atomicMax g_bestA[t]
// q smem layout: slot o = 32m + jj + 8*e4 for d4 = 32m + 4jj + e4
// -> conflict-free LDS.128 across the 8 j-lanes (broadcast across g-groups).
// ---------------------------------------------------------------------------
__global__ void __launch_bounds__(NTHREADS) step_kernel(int t, const float* __restrict__ scales,
                                                        float* __restrict__ d_out,
                                                        unsigned skx, unsigned sky,
                                                        const float* __restrict__ x0,
                                                        const int* __restrict__ seeds) {
    __shared__ uint4 s_qA[256];                     // packed q, b0..3, 4 KB
    __shared__ uint4 s_qB[256];                     // packed q, b4..7, 4 KB
    __shared__ float s_lg[128 * 9];                 // logits [v_local][b], padded
    __shared__ float s_red[NWARPS][8];
    __shared__ float s_bc[8];                       // broadcast: mu / rstd / as
    __shared__ float s_sq[8];                       // Sq[b] (exact in float)
    __shared__ float s_inv[8];                      // 1/as[b]
    __shared__ unsigned long long s_wbest[NWARPS];  // per-warp best key (b = warp>>2)

    const int tid  = threadIdx.x;
    const int warp = tid >> 5;
    const int lane = tid & 31;
    const int l    = t & 3;

    // ================= (gen) inline tile decompression, steps 0-3 =================
    // Block's tile = rows [blockIdx.x*128, +128) of layer l = seeds
    // [l*65536 + blockIdx.x*512, +512). One seed per thread, threads 0-511.
    if (t < 4 && tid < 512) {
        const int sid = l * SEEDS_PER_LAYER + blockIdx.x * 512 + tid;
        unsigned state = ((unsigned)seeds[sid]) & 0xFFFFu;
        uint4* lo = reinterpret_cast<uint4*>(g_wlo + (size_t)sid * 256);
        uint4* hi = reinterpret_cast<uint4*>(g_whi + (size_t)sid * 256);
#pragma unroll 4
        for (int m = 0; m < 16; m++) {
            unsigned wl[4] = {0u, 0u, 0u, 0u};
            unsigned wh[4] = {0u, 0u, 0u, 0u};
#pragma unroll
            for (int e = 0; e < 16; e++) {
                unsigned bl = (state & 0xFFu) ^ 0x80u;          // klo - 128 as s8
                unsigned bh = ((state >> 8) & 0xFFu) ^ 0x80u;   // khi - 128 as s8
                wl[e >> 2] |= bl << ((e & 3) * 8);
                wh[e >> 2] |= bh << ((e & 3) * 8);
                unsigned fb = __popc(state & LFSR_POLY) & 1u;
                state = ((state >> 1) | (fb << 15)) & 0xFFFFu;
            }
            uint4 ul; ul.x = wl[0]; ul.y = wl[1]; ul.z = wl[2]; ul.w = wl[3];
            uint4 uh; uh.x = wh[0]; uh.y = wh[1]; uh.z = wh[2]; uh.w = wh[3];
            __stwt(lo + m, ul);    // write-through: L2 line stays valid + CLEAN
            __stwt(hi + m, uh);
        }
    }

    // ================= inline prep: thread handles ONE d = tid ============
    float v[8];
    {
        const int d = tid;
        if (d < DDIM - t) {
#pragma unroll
            for (int b = 0; b < 8; b++) v[b] = x0[b * DDIM + d + t];
        } else {
            const int s = d + t - DDIM;   // 0..t-1
#pragma unroll
            for (int b = 0; b < 8; b++) v[b] = decode_tok(g_bestA[s * BATCH + b]);
        }
    }

    // ---- mean ----
    float part[8];
#pragma unroll
    for (int b = 0; b < 8; b++) part[b] = v[b];
#pragma unroll
    for (int off = 16; off; off >>= 1)
#pragma unroll
        for (int b = 0; b < 8; b++) part[b] += __shfl_down_sync(0xFFFFFFFFu, part[b], off);
    if (lane == 0)
#pragma unroll
        for (int b = 0; b < 8; b++) s_red[warp][b] = part[b];
    __syncthreads();
    if (warp == 0 && lane < 8) {
        const int b = lane;
        float s = 0.0f;
#pragma unroll
        for (int w = 0; w < NWARPS; w++) s += s_red[w][b];
        s_bc[b] = s * (1.0f / DDIM);
    }
    __syncthreads();
    float mu[8];
#pragma unroll
    for (int b = 0; b < 8; b++) mu[b] = s_bc[b];
    __syncthreads();

    // ---- variance ----
#pragma unroll
    for (int b = 0; b < 8; b++) {
        float d0 = v[b] - mu[b];
        part[b] = d0 * d0;
    }
#pragma unroll
    for (int off = 16; off; off >>= 1)
#pragma unroll
        for (int b = 0; b < 8; b++) part[b] += __shfl_down_sync(0xFFFFFFFFu, part[b], off);
    if (lane == 0)
#pragma unroll
        for (int b = 0; b < 8; b++) s_red[warp][b] = part[b];
    __syncthreads();
    if (warp == 0 && lane < 8) {
        const int b = lane;
        float s = 0.0f;
#pragma unroll
        for (int w = 0; w < NWARPS; w++) s += s_red[w][b];
        s_bc[b] = 1.0f / sqrtf(s * (1.0f / DDIM) + 1e-5f);
    }
    __syncthreads();
    float xn[8];
#pragma unroll
    for (int b = 0; b < 8; b++) xn[b] = (v[b] - mu[b]) * s_bc[b];
    __syncthreads();

    // ---- max |xn| ----
#pragma unroll
    for (int b = 0; b < 8; b++) part[b] = fabsf(xn[b]);
#pragma unroll
    for (int off = 16; off; off >>= 1)
#pragma unroll
        for (int b = 0; b < 8; b++) part[b] = fmaxf(part[b], __shfl_down_sync(0xFFFFFFFFu, part[b], off));
    if (lane == 0)
#pragma unroll
        for (int b = 0; b < 8; b++) s_red[warp][b] = part[b];
    __syncthreads();
    if (warp == 0 && lane < 8) {
        const int b = lane;
        float s = s_red[0][b];
#pragma unroll
        for (int w = 1; w < NWARPS; w++) s = fmaxf(s, s_red[w][b]);
        float as = 127.0f / fmaxf(s, 1e-5f);
        s_bc[b]  = as;
        s_inv[b] = 1.0f / as;
    }
    __syncthreads();

    // ---- int8 quantize ----
    int q[8];
#pragma unroll
    for (int b = 0; b < 8; b++)
        q[b] = (int)rintf(fminf(fmaxf(xn[b] * s_bc[b], -127.0f), 127.0f));

    // ---- Sq[b] reduction (exact in fp32) ----
#pragma unroll
    for (int b = 0; b < 8; b++) part[b] = (float)q[b];
#pragma unroll
    for (int off = 16; off; off >>= 1)
#pragma unroll
        for (int b = 0; b < 8; b++) part[b] += __shfl_down_sync(0xFFFFFFFFu, part[b], off);
    if (lane == 0)
#pragma unroll
        for (int b = 0; b < 8; b++) s_red[warp][b] = part[b];
    __syncthreads();
    if (warp == 0 && lane < 8) {
        const int b = lane;
        float s = 0.0f;
#pragma unroll
        for (int w = 0; w < NWARPS; w++) s += s_red[w][b];
        s_sq[b] = s;
    }

    // ---- pack q (4 consecutive d per u32 via 2 shfl levels), store swizzled ----
    {
        unsigned qd[8];
#pragma unroll
        for (int b = 0; b < 8; b++) {
            unsigned byte = (unsigned)(q[b] & 0xFF);
            unsigned pr   = byte | (__shfl_down_sync(0xFFFFFFFFu, byte, 1) << 8);
            qd[b]         = pr   | (__shfl_down_sync(0xFFFFFFFFu, pr,   2) << 16);
        }
        if ((tid & 3) == 0) {
            const int d4 = tid >> 2;              // 0..255
            const int m  = d4 >> 5;
            const int i  = d4 & 31;
            const int jj = i >> 2;
            const int e4 = i & 3;
            const int o  = 32 * m + jj + 8 * e4;
            uint4 qa, qb;
            qa.x = qd[0]; qa.y = qd[1]; qa.z = qd[2]; qa.w = qd[3];
            qb.x = qd[4]; qb.y = qd[5]; qb.z = qd[6]; qb.w = qd[7];
            s_qA[o] = qa;
            s_qB[o] = qb;
        }
    }
    __syncthreads();

    // ================= dp4a matmul =================
    // warp covers 4 rows; lane (g, j): g = lane>>3 -> row, j = lane&7 -> d-slice
    const int g  = lane >> 3;
    const int j  = lane & 7;
    const int vl = warp * 4 + g;                  // local row, 0..127
    const int v0 = blockIdx.x * 128 + vl;

    const uint4* lo0 = reinterpret_cast<const uint4*>(
        g_wlo + ((size_t)l * VOCAB + v0) * DDIM);   // 64 uint4 per row
    const uint4* hi0 = reinterpret_cast<const uint4*>(
        g_whi + ((size_t)l * VOCAB + v0) * DDIM);

    int accL[8], accH[8];
#pragma unroll
    for (int b = 0; b < 8; b++) { accL[b] = 0; accH[b] = 0; }

#pragma unroll 4
    for (int m = 0; m < 8; m++) {
        const int c = j + 8 * m;                  // uint4 index within row
        uint4 L = __ldcs(lo0 + c);                // streaming: evict-first
        uint4 H = __ldcs(hi0 + c);
        unsigned Lw[4] = {L.x, L.y, L.z, L.w};
        unsigned Hw[4] = {H.x, H.y, H.z, H.w};
#pragma unroll
        for (int e4 = 0; e4 < 4; e4++) {
            const int o = 32 * m + j + 8 * e4;
            const uint4 qa = s_qA[o];
            const uint4 qb = s_qB[o];
            const int qv[8] = {(int)qa.x, (int)qa.y, (int)qa.z, (int)qa.w,
                               (int)qb.x, (int)qb.y, (int)qb.z, (int)qb.w};
            const int wl = (int)Lw[e4];
            const int wh = (int)Hw[e4];
#pragma unroll
            for (int b = 0; b < 8; b++) {
                accL[b] = __dp4a(qv[b], wl, accL[b]);
                accH[b] = __dp4a(qv[b], wh, accH[b]);
            }
        }
    }

    // reduce over the 8 D-slice lanes (groups of 8 within the warp)
#pragma unroll
    for (int b = 0; b < 8; b++) {
        int aL = accL[b], aH = accH[b];
        aL += __shfl_down_sync(0xFFFFFFFFu, aL, 4, 8);
        aL += __shfl_down_sync(0xFFFFFFFFu, aL, 2, 8);
        aL += __shfl_down_sync(0xFFFFFFFFu, aL, 1, 8);
        aH += __shfl_down_sync(0xFFFFFFFFu, aH, 4, 8);
        aH += __shfl_down_sync(0xFFFFFFFFu, aH, 2, 8);
        aH += __shfl_down_sync(0xFFFFFFFFu, aH, 1, 8);
        accL[b] = aL; accH[b] = aH;
    }

    const float cl = scales[l] * (1.0f / 32768.0f);
    if (j == 0) {
        const int vg = v0;
#pragma unroll
        for (int b = 0; b < 8; b++) {
            // k-32768 = 256*khi_s + klo_s + 128
            float S = fmaf(256.0f, (float)accH[b],
                           fmaf(128.0f, s_sq[b], (float)accL[b]));
            float lgv = S * cl * s_inv[b];
            d_out[TOKS_COUNT + ((size_t)t * BATCH + b) * VOCAB + vg] = lgv;
            s_lg[vl * 9 + b] = lgv;
        }
    }
    __syncthreads();

    // ================= fused gumbel + block argmax =================
    {
        const int v_local = tid & 127;
        const int b       = tid >> 7;            // 0..7
        const int vg      = blockIdx.x * 128 + v_local;
        uint2 sk; sk.x = skx; sk.y = sky;

        const unsigned ctr = (unsigned)b * (unsigned)VOCAB + (unsigned)vg;
        uint2 rr = threefry2x32(sk, 0u, ctr);
        unsigned bits = rr.x ^ rr.y;
        float u01 = __uint_as_float((bits >> 9) | 0x3f800000u) - 1.0f;
        float u   = fmaxf(u01, 1.17549435e-38f);
        float gum = -logf(-logf(u));
        float val = s_lg[v_local * 9 + b] + gum;
        unsigned long long key = ((unsigned long long)orderf(val) << 32)
                               | (unsigned long long)(0xFFFFFFFFu - (unsigned)vg);
#pragma unroll
        for (int off = 16; off; off >>= 1) {
            unsigned long long o = __shfl_down_sync(0xFFFFFFFFu, key, off);
            if (o > key) key = o;
        }
        if (lane == 0) s_wbest[warp] = key;      // warp w covers b = w>>2
    }
    __syncthreads();

    // warp 0 merges 32 warps (4 per b) -> 8 per-b bests -> atomicMax
    if (warp == 0) {
        unsigned long long key = s_wbest[lane];  // b = lane>>2
        unsigned long long o = __shfl_down_sync(0xFFFFFFFFu, key, 2, 4);
        if (o > key) key = o;
        o = __shfl_down_sync(0xFFFFFFFFu, key, 1, 4);
        if (o > key) key = o;
        if ((lane & 3) == 0) {
            atomicMax(&g_bestA[t * BATCH + (lane >> 2)], key);
        }
    }
}

// ---------------------------------------------------------------------------
// Kernel 2: final token decode for all steps
// ---------------------------------------------------------------------------
__global__ void finalize_kernel(float* __restrict__ d_out) {
    int i = threadIdx.x;
    if (i < TSTEPS * BATCH) d_out[i] = decode_tok(g_bestA[i]);
}

// ---------------------------------------------------------------------------
// Launch: single stream, 18 nodes. Steps 0-3 decompress their own layer's
// weights inline (block == tile == 512 seeds); steps 4-15 reuse them.
// ---------------------------------------------------------------------------
extern "C" void kernel_launch(void* const* d_in, const int* in_sizes, int n_in,
                              void* d_out, int out_size) {
    const float* x0     = (const float*)d_in[0];   // [8,1024]
    const int*   seeds  = (const int*)d_in[1];     // [4,65536]
    const float* scales = (const float*)d_in[2];   // [4]
    float* out = (float*)d_out;

    // host-side subkey chain (input-independent, deterministic):
    // key_0 = key(1) = (0,1); each step: new_key = tf(key,0,0), sk = tf(key,0,1)
    unsigned skx[TSTEPS], sky[TSTEPS];
    {
        uint2 key; key.x = 0u; key.y = 1u;
        for (int t = 0; t < TSTEPS; t++) {
            uint2 nk = threefry2x32(key, 0u, 0u);
            uint2 sk = threefry2x32(key, 0u, 1u);
            skx[t] = sk.x; sky[t] = sk.y;
            key = nk;
        }
    }

    init_kernel<<<1, 128>>>();
    for (int t = 0; t < TSTEPS; t++) {
        step_kernel<<<VOCAB / 128, NTHREADS>>>(t, scales, out, skx[t], sky[t], x0, seeds);
    }
    finalize_kernel<<<1, 128>>>(out);
}